// round 4
// baseline (speedup 1.0000x reference)
#include <cuda_runtime.h>
#include <cstdint>
#include <cfloat>

// Problem constants (from reference setup_inputs)
#define N_ROWS  131072
#define DIMS    64
#define KENT    4096
#define CK      128      // codebook entries per shared-memory chunk
#define THREADS 256
#define NBLOCKS (N_ROWS / THREADS)   // 512
#define TAU     0.01f    // fp32 margin below which we re-check with ref-emulated arithmetic

// Scratch (no allocations allowed anywhere)
__device__ float g_enorm[KENT];   // fp64-accumulated, rounded once to fp32
__device__ float g_bsum[NBLOCKS];
__device__ int   g_idx[N_ROWS];
__device__ int   g_list[N_ROWS];
__device__ int   g_cnt;

// ---------- packed f32x2 helpers ----------
__device__ __forceinline__ unsigned long long pk2(float a, float b) {
    unsigned long long r;
    asm("mov.b64 %0, {%1, %2};" : "=l"(r) : "f"(a), "f"(b));
    return r;
}
__device__ __forceinline__ void upk2(unsigned long long v, float &a, float &b) {
    asm("mov.b64 {%0, %1}, %2;" : "=f"(a), "=f"(b) : "l"(v));
}
__device__ __forceinline__ void ffma2(unsigned long long &acc,
                                      unsigned long long a, unsigned long long b) {
    asm("fma.rn.f32x2 %0, %1, %2, %0;" : "+l"(acc) : "l"(a), "l"(b));
}

// ---------- kernel 0: codebook norms (fp64 -> fp32) + counter reset ----------
__global__ void vq_init(const float* __restrict__ cb) {
    int k = blockIdx.x * blockDim.x + threadIdx.x;
    if (k == 0) g_cnt = 0;
    if (k < KENT) {
        const float4* p = (const float4*)(cb + (size_t)k * DIMS);
        double s = 0.0;
        #pragma unroll
        for (int i = 0; i < DIMS / 4; i++) {
            float4 v = p[i];
            s += (double)v.x * v.x + (double)v.y * v.y
               + (double)v.z * v.z + (double)v.w * v.w;
        }
        g_enorm[k] = (float)s;
    }
}

// ---------- kernel 1: fast fp32 f32x2 distance scan -> argmin + margin ----------
__global__ __launch_bounds__(THREADS, 2)
void vq_main(const float* __restrict__ x, const float* __restrict__ cb) {
    __shared__ float s_cb[CK * DIMS];
    __shared__ float s_en[CK];

    const int tid = threadIdx.x;
    const int row = blockIdx.x * THREADS + tid;

    unsigned long long xr[DIMS / 2];
    float xnorm = 0.f;
    {
        const float4* xp = (const float4*)(x + (size_t)row * DIMS);
        #pragma unroll
        for (int i = 0; i < DIMS / 4; i++) {
            float4 v = xp[i];
            xr[2 * i]     = pk2(v.x, v.y);
            xr[2 * i + 1] = pk2(v.z, v.w);
            xnorm += v.x * v.x + v.y * v.y;
            xnorm += v.z * v.z + v.w * v.w;
        }
    }

    float best  = FLT_MAX;
    float best2 = FLT_MAX;
    int   bidx  = 0;

    for (int c0 = 0; c0 < KENT; c0 += CK) {
        __syncthreads();
        {
            const float4* gp = (const float4*)(cb + (size_t)c0 * DIMS);
            float4* sp = (float4*)s_cb;
            for (int i = tid; i < CK * DIMS / 4; i += THREADS) sp[i] = gp[i];
            if (tid < CK) s_en[tid] = g_enorm[c0 + tid];
        }
        __syncthreads();

        #pragma unroll 2
        for (int k = 0; k < CK; k++) {
            unsigned long long acc0 = 0ull, acc1 = 0ull;
            const ulonglong2* ep = (const ulonglong2*)(s_cb + k * DIMS);
            #pragma unroll
            for (int i = 0; i < DIMS / 4; i++) {
                ulonglong2 e = ep[i];
                ffma2(acc0, xr[2 * i],     e.x);
                ffma2(acc1, xr[2 * i + 1], e.y);
            }
            float a0, a1, b0, b1;
            upk2(acc0, a0, a1);
            upk2(acc1, b0, b1);
            float dot  = (a0 + a1) + (b0 + b1);
            float dist = (xnorm + s_en[k]) - 2.0f * dot;
            if (dist < best) { best2 = best; best = dist; bidx = c0 + k; }
            else if (dist < best2) { best2 = dist; }
        }
    }

    g_idx[row] = bidx;
    if (best2 - best < TAU) {
        int slot = atomicAdd(&g_cnt, 1);
        g_list[slot] = row;
    }
}

// ---------- kernel 2: reference-emulating fp32 re-scan of marginal rows ----------
// Mimics: dist = fl( fl(xnorm + enorm_k) - 2 * dot32_k ),
// dot32_k = sequential ascending-d fp32 FMA chain (cublas/Eigen order),
// norms = fp64 accumulated, rounded once to fp32 (within ~1 ulp of any fp32 order).
__global__ __launch_bounds__(256, 2)
void vq_refine(const float* __restrict__ x, const float* __restrict__ cb) {
    __shared__ float s_x[DIMS];
    __shared__ float s_best[256];
    __shared__ int   s_idx[256];
    __shared__ float s_xn;

    const int tid = threadIdx.x;
    const int cnt = g_cnt;

    for (int i = blockIdx.x; i < cnt; i += gridDim.x) {
        const int row = g_list[i];
        if (tid < DIMS) s_x[tid] = x[(size_t)row * DIMS + tid];
        __syncthreads();
        if (tid == 0) {
            double xs = 0.0;
            #pragma unroll
            for (int d = 0; d < DIMS; d++) xs += (double)s_x[d] * s_x[d];
            s_xn = (float)xs;
        }
        __syncthreads();
        const float xnorm = s_xn;

        float best = FLT_MAX;
        int   bi   = 0x7fffffff;
        for (int k = tid; k < KENT; k += 256) {
            const float4* e4 = (const float4*)(cb + (size_t)k * DIMS);
            float acc = 0.0f;
            #pragma unroll
            for (int q = 0; q < DIMS / 4; q++) {
                float4 e = e4[q];
                // strict sequential ascending-d chain: data dependency pins the order
                acc = fmaf(s_x[4 * q + 0], e.x, acc);
                acc = fmaf(s_x[4 * q + 1], e.y, acc);
                acc = fmaf(s_x[4 * q + 2], e.z, acc);
                acc = fmaf(s_x[4 * q + 3], e.w, acc);
            }
            float t    = xnorm + g_enorm[k];
            float dist = t - 2.0f * acc;
            if (dist < best) { best = dist; bi = k; }   // ascending k => first-min
        }
        s_best[tid] = best;
        s_idx[tid]  = bi;
        __syncthreads();
        for (int off = 128; off > 0; off >>= 1) {
            if (tid < off) {
                float ov = s_best[tid + off];
                int   oi = s_idx[tid + off];
                if (ov < s_best[tid] || (ov == s_best[tid] && oi < s_idx[tid])) {
                    s_best[tid] = ov;
                    s_idx[tid]  = oi;
                }
            }
            __syncthreads();
        }
        if (tid == 0) g_idx[row] = s_idx[0];
        __syncthreads();
    }
}

// ---------- kernel 3: gather winner, straight-through output, loss partials ----------
__global__ __launch_bounds__(THREADS)
void vq_epi(const float* __restrict__ x, const float* __restrict__ y,
            const float* __restrict__ cb, float* __restrict__ out) {
    __shared__ float s_red[THREADS / 32];

    const int tid = threadIdx.x;
    const int row = blockIdx.x * THREADS + tid;
    const int bidx = g_idx[row];

    float ls = 0.f;
    const float4* xp = (const float4*)(x  + (size_t)row  * DIMS);
    const float4* yp = (const float4*)(y  + (size_t)row  * DIMS);
    const float4* ep = (const float4*)(cb + (size_t)bidx * DIMS);
    float4*       op = (float4*)(out + (size_t)row * DIMS);

    #pragma unroll
    for (int i = 0; i < DIMS / 4; i++) {
        float4 xv = xp[i];
        float4 yv = yp[i];
        float4 e  = ep[i];

        float d;
        d = e.x - xv.x; ls += d * d;  d = e.x - yv.x; ls += d * d;
        d = e.y - xv.y; ls += d * d;  d = e.y - yv.y; ls += d * d;
        d = e.z - xv.z; ls += d * d;  d = e.z - yv.z; ls += d * d;
        d = e.w - xv.w; ls += d * d;  d = e.w - yv.w; ls += d * d;

        // straight-through estimator, mirroring reference rounding: a + (q - a)
        float4 o;
        float a;
        a = xv.x + yv.x; o.x = a + (e.x - a);
        a = xv.y + yv.y; o.y = a + (e.y - a);
        a = xv.z + yv.z; o.z = a + (e.z - a);
        a = xv.w + yv.w; o.w = a + (e.w - a);
        op[i] = o;
    }

    #pragma unroll
    for (int off = 16; off > 0; off >>= 1)
        ls += __shfl_xor_sync(0xffffffffu, ls, off);
    if ((tid & 31) == 0) s_red[tid >> 5] = ls;
    __syncthreads();
    if (tid == 0) {
        float s = 0.f;
        #pragma unroll
        for (int w = 0; w < THREADS / 32; w++) s += s_red[w];
        g_bsum[blockIdx.x] = s;
    }
}

// ---------- kernel 4: deterministic final loss ----------
__global__ void vq_fin(float* __restrict__ out) {
    if (threadIdx.x == 0 && blockIdx.x == 0) {
        double acc = 0.0;
        for (int i = 0; i < NBLOCKS; i++) acc += (double)g_bsum[i];
        double loss = 1.25 * acc / (double)((size_t)N_ROWS * DIMS);
        out[(size_t)N_ROWS * DIMS] = (float)loss;
    }
}

extern "C" void kernel_launch(void* const* d_in, const int* in_sizes, int n_in,
                              void* d_out, int out_size) {
    const float* x  = (const float*)d_in[0];
    const float* y  = (const float*)d_in[1];
    const float* cb = (const float*)d_in[2];
    float* out = (float*)d_out;

    vq_init<<<(KENT + 255) / 256, 256>>>(cb);
    vq_main<<<NBLOCKS, THREADS>>>(x, cb);
    vq_refine<<<64, 256>>>(x, cb);
    vq_epi<<<NBLOCKS, THREADS>>>(x, y, cb, out);
    vq_fin<<<1, 1>>>(out);
}

// round 5
// speedup vs baseline: 1.1401x; 1.1401x over previous
#include <cuda_runtime.h>
#include <cstdint>
#include <cfloat>

// Problem constants (from reference setup_inputs)
#define N_ROWS  131072
#define DIMS    64
#define KENT    4096
#define CK      128       // codebook entries per shared-memory chunk
#define MTHREADS 128      // vq_main threads per block (each handles 2 rows)
#define ROWS_PER_BLOCK 256
#define MBLOCKS (N_ROWS / ROWS_PER_BLOCK)   // 512
#define ETHREADS 256      // vq_epi threads per block
#define EBLOCKS (N_ROWS / ETHREADS)         // 512
#define TAU     0.01f     // fp32 margin below which we re-check with ref-emulated arithmetic

// Scratch (no allocations allowed anywhere)
__device__ float g_enorm[KENT];   // fp64-accumulated, rounded once to fp32
__device__ float g_bsum[EBLOCKS];
__device__ int   g_idx[N_ROWS];
__device__ int   g_list[N_ROWS];
__device__ int   g_cnt;

// ---------- packed f32x2 helpers ----------
__device__ __forceinline__ unsigned long long pk2(float a, float b) {
    unsigned long long r;
    asm("mov.b64 %0, {%1, %2};" : "=l"(r) : "f"(a), "f"(b));
    return r;
}
__device__ __forceinline__ void upk2(unsigned long long v, float &a, float &b) {
    asm("mov.b64 {%0, %1}, %2;" : "=f"(a), "=f"(b) : "l"(v));
}
__device__ __forceinline__ void ffma2(unsigned long long &acc,
                                      unsigned long long a, unsigned long long b) {
    asm("fma.rn.f32x2 %0, %1, %2, %0;" : "+l"(acc) : "l"(a), "l"(b));
}

// ---------- kernel 0: codebook norms (fp64 -> fp32) + counter reset ----------
__global__ void vq_init(const float* __restrict__ cb) {
    int k = blockIdx.x * blockDim.x + threadIdx.x;
    if (k == 0) g_cnt = 0;
    if (k < KENT) {
        const float4* p = (const float4*)(cb + (size_t)k * DIMS);
        double s = 0.0;
        #pragma unroll
        for (int i = 0; i < DIMS / 4; i++) {
            float4 v = p[i];
            s += (double)v.x * v.x + (double)v.y * v.y
               + (double)v.z * v.z + (double)v.w * v.w;
        }
        g_enorm[k] = (float)s;
    }
}

// ---------- kernel 1: fp32 f32x2 scan, 2 rows per thread -> argmin + margin ----------
__global__ __launch_bounds__(MTHREADS, 2)
void vq_main(const float* __restrict__ x, const float* __restrict__ cb) {
    __shared__ float s_cb[CK * DIMS];
    __shared__ float s_en[CK];

    const int tid  = threadIdx.x;
    const int row0 = blockIdx.x * ROWS_PER_BLOCK + tid;            // rows [base, base+128)
    const int row1 = row0 + MTHREADS;                              // rows [base+128, base+256)

    unsigned long long xr0[DIMS / 2], xr1[DIMS / 2];
    float xn0 = 0.f, xn1 = 0.f;
    {
        const float4* xp0 = (const float4*)(x + (size_t)row0 * DIMS);
        const float4* xp1 = (const float4*)(x + (size_t)row1 * DIMS);
        #pragma unroll
        for (int i = 0; i < DIMS / 4; i++) {
            float4 v = xp0[i];
            xr0[2 * i]     = pk2(v.x, v.y);
            xr0[2 * i + 1] = pk2(v.z, v.w);
            xn0 += v.x * v.x + v.y * v.y;
            xn0 += v.z * v.z + v.w * v.w;
            float4 w = xp1[i];
            xr1[2 * i]     = pk2(w.x, w.y);
            xr1[2 * i + 1] = pk2(w.z, w.w);
            xn1 += w.x * w.x + w.y * w.y;
            xn1 += w.z * w.z + w.w * w.w;
        }
    }

    float best0  = FLT_MAX, best20 = FLT_MAX;
    float best1  = FLT_MAX, best21 = FLT_MAX;
    int   bidx0  = 0,       bidx1  = 0;

    for (int c0 = 0; c0 < KENT; c0 += CK) {
        __syncthreads();
        {
            const float4* gp = (const float4*)(cb + (size_t)c0 * DIMS);
            float4* sp = (float4*)s_cb;
            #pragma unroll
            for (int j = 0; j < CK * DIMS / 4 / MTHREADS; j++)
                sp[tid + j * MTHREADS] = gp[tid + j * MTHREADS];
            if (tid < CK) s_en[tid] = g_enorm[c0 + tid];
        }
        __syncthreads();

        #pragma unroll 2
        for (int k = 0; k < CK; k++) {
            unsigned long long a00 = 0ull, a01 = 0ull, a10 = 0ull, a11 = 0ull;
            const ulonglong2* ep = (const ulonglong2*)(s_cb + k * DIMS);
            #pragma unroll
            for (int i = 0; i < DIMS / 4; i++) {
                ulonglong2 e = ep[i];          // LDS.128, warp-broadcast (k uniform)
                ffma2(a00, xr0[2 * i],     e.x);
                ffma2(a01, xr0[2 * i + 1], e.y);
                ffma2(a10, xr1[2 * i],     e.x);
                ffma2(a11, xr1[2 * i + 1], e.y);
            }
            const float en = s_en[k];
            {
                float p0, p1, q0, q1;
                upk2(a00, p0, p1);
                upk2(a01, q0, q1);
                float dot  = (p0 + p1) + (q0 + q1);
                float dist = (xn0 + en) - 2.0f * dot;
                if (dist < best0) { best20 = best0; best0 = dist; bidx0 = c0 + k; }
                else if (dist < best20) { best20 = dist; }
            }
            {
                float p0, p1, q0, q1;
                upk2(a10, p0, p1);
                upk2(a11, q0, q1);
                float dot  = (p0 + p1) + (q0 + q1);
                float dist = (xn1 + en) - 2.0f * dot;
                if (dist < best1) { best21 = best1; best1 = dist; bidx1 = c0 + k; }
                else if (dist < best21) { best21 = dist; }
            }
        }
    }

    g_idx[row0] = bidx0;
    g_idx[row1] = bidx1;
    if (best20 - best0 < TAU) { int s = atomicAdd(&g_cnt, 1); g_list[s] = row0; }
    if (best21 - best1 < TAU) { int s = atomicAdd(&g_cnt, 1); g_list[s] = row1; }
}

// ---------- kernel 2: reference-emulating fp32 re-scan of marginal rows ----------
// Mimics: dist = fl( fl(xnorm + enorm_k) - 2 * dot32_k ),
// dot32_k = sequential ascending-d fp32 FMA chain (cublas/Eigen order),
// norms = fp64 accumulated, rounded once to fp32.
__global__ __launch_bounds__(256, 2)
void vq_refine(const float* __restrict__ x, const float* __restrict__ cb) {
    __shared__ float s_x[DIMS];
    __shared__ float s_best[256];
    __shared__ int   s_idx[256];
    __shared__ float s_xn;

    const int tid = threadIdx.x;
    const int cnt = g_cnt;

    for (int i = blockIdx.x; i < cnt; i += gridDim.x) {
        const int row = g_list[i];
        if (tid < DIMS) s_x[tid] = x[(size_t)row * DIMS + tid];
        __syncthreads();
        if (tid == 0) {
            double xs = 0.0;
            #pragma unroll
            for (int d = 0; d < DIMS; d++) xs += (double)s_x[d] * s_x[d];
            s_xn = (float)xs;
        }
        __syncthreads();
        const float xnorm = s_xn;

        float best = FLT_MAX;
        int   bi   = 0x7fffffff;
        for (int k = tid; k < KENT; k += 256) {
            const float4* e4 = (const float4*)(cb + (size_t)k * DIMS);
            float acc = 0.0f;
            #pragma unroll
            for (int q = 0; q < DIMS / 4; q++) {
                float4 e = e4[q];
                // strict sequential ascending-d chain: data dependency pins the order
                acc = fmaf(s_x[4 * q + 0], e.x, acc);
                acc = fmaf(s_x[4 * q + 1], e.y, acc);
                acc = fmaf(s_x[4 * q + 2], e.z, acc);
                acc = fmaf(s_x[4 * q + 3], e.w, acc);
            }
            float t    = xnorm + g_enorm[k];
            float dist = t - 2.0f * acc;
            if (dist < best) { best = dist; bi = k; }   // ascending k => first-min
        }
        s_best[tid] = best;
        s_idx[tid]  = bi;
        __syncthreads();
        for (int off = 128; off > 0; off >>= 1) {
            if (tid < off) {
                float ov = s_best[tid + off];
                int   oi = s_idx[tid + off];
                if (ov < s_best[tid] || (ov == s_best[tid] && oi < s_idx[tid])) {
                    s_best[tid] = ov;
                    s_idx[tid]  = oi;
                }
            }
            __syncthreads();
        }
        if (tid == 0) g_idx[row] = s_idx[0];
        __syncthreads();
    }
}

// ---------- kernel 3: gather winner, straight-through output, loss partials ----------
__global__ __launch_bounds__(ETHREADS)
void vq_epi(const float* __restrict__ x, const float* __restrict__ y,
            const float* __restrict__ cb, float* __restrict__ out) {
    __shared__ float s_red[ETHREADS / 32];

    const int tid = threadIdx.x;
    const int row = blockIdx.x * ETHREADS + tid;
    const int bidx = g_idx[row];

    float ls = 0.f;
    const float4* xp = (const float4*)(x  + (size_t)row  * DIMS);
    const float4* yp = (const float4*)(y  + (size_t)row  * DIMS);
    const float4* ep = (const float4*)(cb + (size_t)bidx * DIMS);
    float4*       op = (float4*)(out + (size_t)row * DIMS);

    #pragma unroll
    for (int i = 0; i < DIMS / 4; i++) {
        float4 xv = xp[i];
        float4 yv = yp[i];
        float4 e  = ep[i];

        float d;
        d = e.x - xv.x; ls += d * d;  d = e.x - yv.x; ls += d * d;
        d = e.y - xv.y; ls += d * d;  d = e.y - yv.y; ls += d * d;
        d = e.z - xv.z; ls += d * d;  d = e.z - yv.z; ls += d * d;
        d = e.w - xv.w; ls += d * d;  d = e.w - yv.w; ls += d * d;

        // straight-through estimator, mirroring reference rounding: a + (q - a)
        float4 o;
        float a;
        a = xv.x + yv.x; o.x = a + (e.x - a);
        a = xv.y + yv.y; o.y = a + (e.y - a);
        a = xv.z + yv.z; o.z = a + (e.z - a);
        a = xv.w + yv.w; o.w = a + (e.w - a);
        op[i] = o;
    }

    #pragma unroll
    for (int off = 16; off > 0; off >>= 1)
        ls += __shfl_xor_sync(0xffffffffu, ls, off);
    if ((tid & 31) == 0) s_red[tid >> 5] = ls;
    __syncthreads();
    if (tid == 0) {
        float s = 0.f;
        #pragma unroll
        for (int w = 0; w < ETHREADS / 32; w++) s += s_red[w];
        g_bsum[blockIdx.x] = s;
    }
}

// ---------- kernel 4: deterministic final loss ----------
__global__ void vq_fin(float* __restrict__ out) {
    if (threadIdx.x == 0 && blockIdx.x == 0) {
        double acc = 0.0;
        for (int i = 0; i < EBLOCKS; i++) acc += (double)g_bsum[i];
        double loss = 1.25 * acc / (double)((size_t)N_ROWS * DIMS);
        out[(size_t)N_ROWS * DIMS] = (float)loss;
    }
}

extern "C" void kernel_launch(void* const* d_in, const int* in_sizes, int n_in,
                              void* d_out, int out_size) {
    const float* x  = (const float*)d_in[0];
    const float* y  = (const float*)d_in[1];
    const float* cb = (const float*)d_in[2];
    float* out = (float*)d_out;

    vq_init<<<(KENT + 255) / 256, 256>>>(cb);
    vq_main<<<MBLOCKS, MTHREADS>>>(x, cb);
    vq_refine<<<64, 256>>>(x, cb);
    vq_epi<<<EBLOCKS, ETHREADS>>>(x, y, cb, out);
    vq_fin<<<1, 1>>>(out);
}

// round 7
// speedup vs baseline: 2.0702x; 1.8158x over previous
#include <cuda_runtime.h>
#include <cuda_bf16.h>
#include <cstdint>
#include <cfloat>

// Problem constants
#define N_ROWS  131072
#define DIMS    64
#define KENT    4096
#define GK      192            // [xh|xh|xl] . [eh|el|eh]
#define GM      128            // rows per CTA
#define GN      64             // codes per chunk
#define NCHUNK  (KENT / GN)    // 64
#define GBLOCKS (N_ROWS / GM)  // 1024
#define ETHREADS 256
#define EBLOCKS (N_ROWS / ETHREADS)
#define TAU     0.01f

// smem layout (bytes): padded row stride 400B (200 bf16) -> LDSM conflict-free
#define SROW    400
#define A_OFF   0
#define A_BYTES (GM * SROW)            // 51200
#define B_OFF   A_BYTES
#define B_BYTES (GN * SROW)            // 25600 per buffer
#define EN_OFF  (B_OFF + 2 * B_BYTES)  // 102400
#define SMEM_TOTAL (EN_OFF + 2 * 256)  // 102912

// Scratch
__device__ __nv_bfloat16 g_bcat[(size_t)KENT * GK];   // 1.5 MB
__device__ float g_enorm[KENT];
__device__ float g_en2[KENT];
__device__ float g_bsum[EBLOCKS];
__device__ int   g_idx[N_ROWS];
__device__ int   g_list[N_ROWS];
__device__ int   g_cnt;

// ---------------- PTX helpers (plain sm_103-safe: mma.sync / ldmatrix / cp.async) ----
__device__ __forceinline__ uint32_t smem_u32(const void* p) {
    uint32_t a;
    asm("{ .reg .u64 t; cvta.to.shared.u64 t, %1; cvt.u32.u64 %0, t; }" : "=r"(a) : "l"(p));
    return a;
}
#define CP_ASYNC16(dst, src) \
    asm volatile("cp.async.cg.shared.global [%0], [%1], 16;" :: "r"(dst), "l"(src))
#define CP_COMMIT() asm volatile("cp.async.commit_group;" ::: "memory")
#define CP_WAIT(n)  asm volatile("cp.async.wait_group %0;" :: "n"(n) : "memory")

#define LDSM4(r0, r1, r2, r3, a) \
    asm volatile("ldmatrix.sync.aligned.m8n8.x4.shared.b16 {%0,%1,%2,%3}, [%4];" \
        : "=r"(r0), "=r"(r1), "=r"(r2), "=r"(r3) : "r"(a))

#define MMA16816(d, a, b0_, b1_) \
    asm volatile("mma.sync.aligned.m16n8k16.row.col.f32.bf16.bf16.f32 " \
        "{%0,%1,%2,%3}, {%4,%5,%6,%7}, {%8,%9}, {%0,%1,%2,%3};" \
        : "+f"((d)[0]), "+f"((d)[1]), "+f"((d)[2]), "+f"((d)[3]) \
        : "r"((a)[0]), "r"((a)[1]), "r"((a)[2]), "r"((a)[3]), "r"(b0_), "r"(b1_))

__device__ __forceinline__ void upd(float& b, float& b2, int& id, float g, int c) {
    if (g > b) { b2 = b; b = g; id = c; }
    else if (g > b2) { b2 = g; }
}

// ---------- kernel 0: codebook norms (fp64->fp32), -en/2 table, counter reset ----------
__global__ void vq_init(const float* __restrict__ cb) {
    int k = blockIdx.x * blockDim.x + threadIdx.x;
    if (k == 0) g_cnt = 0;
    if (k < KENT) {
        const float4* p = (const float4*)(cb + (size_t)k * DIMS);
        double s = 0.0;
        #pragma unroll
        for (int i = 0; i < DIMS / 4; i++) {
            float4 v = p[i];
            s += (double)v.x * v.x + (double)v.y * v.y
               + (double)v.z * v.z + (double)v.w * v.w;
        }
        g_enorm[k] = (float)s;
        g_en2[k]   = (float)(-0.5 * s);
    }
}

// ---------- prep B: cb -> [eh | el | eh] bf16, K-major per code ----------
__global__ void vq_prep_cb(const float* __restrict__ cb) {
    int k = blockIdx.x * blockDim.x + threadIdx.x;
    if (k >= KENT) return;
    const float* e = cb + (size_t)k * DIMS;
    __nv_bfloat16* b = g_bcat + (size_t)k * GK;
    #pragma unroll
    for (int d = 0; d < DIMS; d++) {
        float v = e[d];
        __nv_bfloat16 h = __float2bfloat16(v);
        float lo = v - __bfloat162float(h);
        b[d]       = h;
        b[64 + d]  = __float2bfloat16(lo);
        b[128 + d] = h;
    }
}

// ---------- main: HMMA distance GEMM + fused per-row argmax ----------
// g[m][n] = xh.eh + xh.el + xl.eh - ||e_n||^2/2 ; argmax_n g == argmin_n dist
__global__ __launch_bounds__(256, 2)
void vq_gemm(const float* __restrict__ x) {
    extern __shared__ char dsm[];
    const int tid  = threadIdx.x;
    const int wid  = tid >> 5;       // 0..7, warp owns rows wid*16..wid*16+15
    const int lane = tid & 31;

    const uint32_t S = smem_u32(dsm);
    const uint32_t A_s = S + A_OFF;

    // ---- build A tile in smem: [xh | xh | xl], padded stride ----
    {
        const int rbase = blockIdx.x * GM;
        for (int idx = tid; idx < GM * DIMS; idx += 256) {
            int r = idx >> 6, d = idx & 63;
            float v = x[(size_t)(rbase + r) * DIMS + d];
            __nv_bfloat16 h = __float2bfloat16(v);
            __nv_bfloat16 l = __float2bfloat16(v - __bfloat162float(h));
            char* row = dsm + A_OFF + r * SROW;
            *(__nv_bfloat16*)(row + 2 * d)       = h;
            *(__nv_bfloat16*)(row + 128 + 2 * d) = h;
            *(__nv_bfloat16*)(row + 256 + 2 * d) = l;
        }
    }

    // ---- prologue: chunk 0 B + en2 ----
    {
        const char* Bg = (const char*)g_bcat;           // chunk 0
        uint32_t Bs = S + B_OFF;
        for (int c = tid; c < GN * 24; c += 256) {
            int rowb = c / 24, seg = c % 24;
            CP_ASYNC16(Bs + rowb * SROW + seg * 16, Bg + rowb * (GK * 2) + seg * 16);
        }
        if (tid < 16) CP_ASYNC16(S + EN_OFF + tid * 16, (const char*)g_en2 + tid * 16);
        CP_COMMIT();
        CP_WAIT(0);
    }
    __syncthreads();

    // ---- hoist A fragments (12 k-steps x 4 regs) ----
    uint32_t af[12][4];
    {
        uint32_t a_base = A_s + (uint32_t)(wid * 16 + (lane & 15)) * SROW + (uint32_t)(lane >> 4) * 16;
        #pragma unroll
        for (int k = 0; k < 12; k++)
            LDSM4(af[k][0], af[k][1], af[k][2], af[k][3], a_base + k * 32);
    }

    // B ldmatrix per-thread address components
    const uint32_t n_part  = (lane & 7) + ((lane >> 4) & 1) * 8;
    const uint32_t koff_b  = ((lane >> 3) & 1) * 16;

    float bestA = -FLT_MAX, best2A = -FLT_MAX;
    float bestB = -FLT_MAX, best2B = -FLT_MAX;
    int   idxA = 0, idxB = 0;

    for (int i = 0; i < NCHUNK; i++) {
        const int buf = i & 1;

        // prefetch chunk i+1 into buf^1
        if (i + 1 < NCHUNK) {
            const char* Bg = (const char*)(g_bcat + (size_t)(i + 1) * GN * GK);
            uint32_t Bs = S + B_OFF + (buf ^ 1) * B_BYTES;
            for (int c = tid; c < GN * 24; c += 256) {
                int rowb = c / 24, seg = c % 24;
                CP_ASYNC16(Bs + rowb * SROW + seg * 16, Bg + rowb * (GK * 2) + seg * 16);
            }
            if (tid < 16)
                CP_ASYNC16(S + EN_OFF + (buf ^ 1) * 256 + tid * 16,
                           (const char*)(g_en2 + (i + 1) * GN) + tid * 16);
            CP_COMMIT();
            CP_WAIT(1);
        } else {
            CP_WAIT(0);
        }
        __syncthreads();

        // ---- compute: 12 k-steps x 8 n-tiles ----
        float d[8][4];
        #pragma unroll
        for (int t = 0; t < 8; t++)
            #pragma unroll
            for (int q = 0; q < 4; q++) d[t][q] = 0.0f;

        const uint32_t Bs = S + B_OFF + buf * B_BYTES;
        #pragma unroll
        for (int k = 0; k < 12; k++) {
            #pragma unroll
            for (int jp = 0; jp < 4; jp++) {
                uint32_t b0, b1, b2, b3;
                LDSM4(b0, b1, b2, b3, Bs + (16 * jp + n_part) * SROW + k * 32 + koff_b);
                MMA16816(d[2 * jp],     af[k], b0, b1);
                MMA16816(d[2 * jp + 1], af[k], b2, b3);
            }
        }

        // ---- epilogue: g = d - en/2; update per-row top-2 ----
        const float* en2s = (const float*)(dsm + EN_OFF + buf * 256);
        const int c_base = i * GN + (lane & 3) * 2;
        #pragma unroll
        for (int t = 0; t < 8; t++) {
            int col0 = t * 8 + (lane & 3) * 2;
            float e0 = en2s[col0], e1 = en2s[col0 + 1];
            int c0 = c_base + t * 8;
            upd(bestA, best2A, idxA, d[t][0] + e0, c0);
            upd(bestA, best2A, idxA, d[t][1] + e1, c0 + 1);
            upd(bestB, best2B, idxB, d[t][2] + e0, c0);
            upd(bestB, best2B, idxB, d[t][3] + e1, c0 + 1);
        }
        __syncthreads();   // protect buf^1 before next iteration's prefetch
    }

    // ---- merge top-2 across the 4 lanes of each quad ----
    #pragma unroll
    for (int s = 1; s <= 2; s <<= 1) {
        float ob  = __shfl_xor_sync(0xffffffffu, bestA,  s);
        float ob2 = __shfl_xor_sync(0xffffffffu, best2A, s);
        int   oi  = __shfl_xor_sync(0xffffffffu, idxA,   s);
        if (ob > bestA) { best2A = fmaxf(bestA, ob2); bestA = ob; idxA = oi; }
        else            { best2A = fmaxf(best2A, ob); }
        ob  = __shfl_xor_sync(0xffffffffu, bestB,  s);
        ob2 = __shfl_xor_sync(0xffffffffu, best2B, s);
        oi  = __shfl_xor_sync(0xffffffffu, idxB,   s);
        if (ob > bestB) { best2B = fmaxf(bestB, ob2); bestB = ob; idxB = oi; }
        else            { best2B = fmaxf(best2B, ob); }
    }

    if ((lane & 3) == 0) {
        const int q  = lane >> 2;
        const int mA = blockIdx.x * GM + wid * 16 + q;
        const int mB = mA + 8;
        g_idx[mA] = idxA;
        g_idx[mB] = idxB;
        // dist = xnorm - 2g  =>  margin_dist = 2*(best - best2)
        if (2.0f * (bestA - best2A) < TAU) { int s = atomicAdd(&g_cnt, 1); g_list[s] = mA; }
        if (2.0f * (bestB - best2B) < TAU) { int s = atomicAdd(&g_cnt, 1); g_list[s] = mB; }
    }
}

// ---------- refine: reference-emulating fp32 re-scan of marginal rows ----------
__global__ __launch_bounds__(256, 2)
void vq_refine(const float* __restrict__ x, const float* __restrict__ cb) {
    __shared__ float s_x[DIMS];
    __shared__ float s_best[256];
    __shared__ int   s_idx[256];
    __shared__ float s_xn;

    const int tid = threadIdx.x;
    const int cnt = g_cnt;

    for (int i = blockIdx.x; i < cnt; i += gridDim.x) {
        const int row = g_list[i];
        if (tid < DIMS) s_x[tid] = x[(size_t)row * DIMS + tid];
        __syncthreads();
        if (tid == 0) {
            double xs = 0.0;
            #pragma unroll
            for (int d = 0; d < DIMS; d++) xs += (double)s_x[d] * s_x[d];
            s_xn = (float)xs;
        }
        __syncthreads();
        const float xnorm = s_xn;

        float best = FLT_MAX;
        int   bi   = 0x7fffffff;
        for (int k = tid; k < KENT; k += 256) {
            const float4* e4 = (const float4*)(cb + (size_t)k * DIMS);
            float acc = 0.0f;
            #pragma unroll
            for (int q = 0; q < DIMS / 4; q++) {
                float4 e = e4[q];
                acc = fmaf(s_x[4 * q + 0], e.x, acc);
                acc = fmaf(s_x[4 * q + 1], e.y, acc);
                acc = fmaf(s_x[4 * q + 2], e.z, acc);
                acc = fmaf(s_x[4 * q + 3], e.w, acc);
            }
            float t    = xnorm + g_enorm[k];
            float dist = t - 2.0f * acc;
            if (dist < best) { best = dist; bi = k; }
        }
        s_best[tid] = best;
        s_idx[tid]  = bi;
        __syncthreads();
        for (int off = 128; off > 0; off >>= 1) {
            if (tid < off) {
                float ov = s_best[tid + off];
                int   oi = s_idx[tid + off];
                if (ov < s_best[tid] || (ov == s_best[tid] && oi < s_idx[tid])) {
                    s_best[tid] = ov;
                    s_idx[tid]  = oi;
                }
            }
            __syncthreads();
        }
        if (tid == 0) g_idx[row] = s_idx[0];
        __syncthreads();
    }
}

// ---------- epilogue: gather winner, straight-through output, loss partials ----------
__global__ __launch_bounds__(ETHREADS)
void vq_epi(const float* __restrict__ x, const float* __restrict__ y,
            const float* __restrict__ cb, float* __restrict__ out) {
    __shared__ float s_red[ETHREADS / 32];

    const int tid = threadIdx.x;
    const int row = blockIdx.x * ETHREADS + tid;
    const int bidx = g_idx[row];

    float ls = 0.f;
    const float4* xp = (const float4*)(x  + (size_t)row  * DIMS);
    const float4* yp = (const float4*)(y  + (size_t)row  * DIMS);
    const float4* ep = (const float4*)(cb + (size_t)bidx * DIMS);
    float4*       op = (float4*)(out + (size_t)row * DIMS);

    #pragma unroll
    for (int i = 0; i < DIMS / 4; i++) {
        float4 xv = xp[i];
        float4 yv = yp[i];
        float4 e  = ep[i];

        float d;
        d = e.x - xv.x; ls += d * d;  d = e.x - yv.x; ls += d * d;
        d = e.y - xv.y; ls += d * d;  d = e.y - yv.y; ls += d * d;
        d = e.z - xv.z; ls += d * d;  d = e.z - yv.z; ls += d * d;
        d = e.w - xv.w; ls += d * d;  d = e.w - yv.w; ls += d * d;

        float4 o;
        float a;
        a = xv.x + yv.x; o.x = a + (e.x - a);
        a = xv.y + yv.y; o.y = a + (e.y - a);
        a = xv.z + yv.z; o.z = a + (e.z - a);
        a = xv.w + yv.w; o.w = a + (e.w - a);
        op[i] = o;
    }

    #pragma unroll
    for (int off = 16; off > 0; off >>= 1)
        ls += __shfl_xor_sync(0xffffffffu, ls, off);
    if ((tid & 31) == 0) s_red[tid >> 5] = ls;
    __syncthreads();
    if (tid == 0) {
        float s = 0.f;
        #pragma unroll
        for (int w = 0; w < ETHREADS / 32; w++) s += s_red[w];
        g_bsum[blockIdx.x] = s;
    }
}

// ---------- deterministic final loss ----------
__global__ void vq_fin(float* __restrict__ out) {
    if (threadIdx.x == 0 && blockIdx.x == 0) {
        double acc = 0.0;
        for (int i = 0; i < EBLOCKS; i++) acc += (double)g_bsum[i];
        double loss = 1.25 * acc / (double)((size_t)N_ROWS * DIMS);
        out[(size_t)N_ROWS * DIMS] = (float)loss;
    }
}

extern "C" void kernel_launch(void* const* d_in, const int* in_sizes, int n_in,
                              void* d_out, int out_size) {
    const float* x  = (const float*)d_in[0];
    const float* y  = (const float*)d_in[1];
    const float* cb = (const float*)d_in[2];
    float* out = (float*)d_out;

    static int smem_set = 0;
    if (!smem_set) {
        cudaFuncSetAttribute(vq_gemm, cudaFuncAttributeMaxDynamicSharedMemorySize, SMEM_TOTAL);
        smem_set = 1;
    }

    vq_init<<<(KENT + 255) / 256, 256>>>(cb);
    vq_prep_cb<<<(KENT + 255) / 256, 256>>>(cb);
    vq_gemm<<<GBLOCKS, 256, SMEM_TOTAL>>>(x);
    vq_refine<<<64, 256>>>(x, cb);
    vq_epi<<<EBLOCKS, ETHREADS>>>(x, y, cb, out);
    vq_fin<<<1, 1>>>(out);
}